// round 5
// baseline (speedup 1.0000x reference)
#include <cuda_runtime.h>
#include <cstdint>

// TT layer via merged-core tf32 mma.sync GEMMs, K-permuted operands for
// vectorized (LDS.128) fragment loads, 256x128 CTA tile / 64x64 warp tile.
// out[n,ab,cd] = relu( sum H12[ab,(s,ij)] x[n,ij,kl] H34[(cd,s),kl] + bias )
// GEMM1 per n: M1[cds, ij] = H34 . Xr[n]^T   M=1024 N=256 K=256
// GEMM2 per n: out[ab, cd] = H12 . M1[n]^T   M=256  N=256 K=1024 (+bias,relu)
// Every operand's K dim is permuted within 32-blocks: p = (k%4)*8 + k/4.

__device__ float g_H34[262144];
__device__ float g_H12[262144];
__device__ float g_Xr[67108864];   // RNA-rounded, K-permuted x (256 MB)
__device__ float g_M1[268435456];  // K-permuted M1 (1 GiB)

__device__ __forceinline__ float rna_tf32(float f) {
  uint32_t r; asm("cvt.rna.tf32.f32 %0, %1;" : "=r"(r) : "f"(f));
  return __uint_as_float(r);
}
__device__ __forceinline__ int perm32(int v) { return ((v & 3) << 3) | (v >> 2); }
__device__ __forceinline__ uint32_t smem_u32(const void* p) {
  uint32_t a;
  asm("{ .reg .u64 t; cvta.to.shared.u64 t, %1; cvt.u32.u64 %0, t; }" : "=r"(a) : "l"(p));
  return a;
}
__device__ __forceinline__ void cp16(uint32_t s, const float* g) {
  asm volatile("cp.async.cg.shared.global [%0], [%1], 16;" :: "r"(s), "l"(g));
}
__device__ __forceinline__ void mma_tf32(float* c, const uint32_t* a, const uint32_t* b) {
  asm volatile(
      "mma.sync.aligned.m16n8k8.row.col.f32.tf32.tf32.f32 "
      "{%0,%1,%2,%3}, {%4,%5,%6,%7}, {%8,%9}, {%0,%1,%2,%3};"
      : "+f"(c[0]), "+f"(c[1]), "+f"(c[2]), "+f"(c[3])
      : "r"(a[0]), "r"(a[1]), "r"(a[2]), "r"(a[3]), "r"(b[0]), "r"(b[1]));
}

// ---------------- precompute (RNA-round + K-permute) ----------------
__global__ void prep_h34(const float* __restrict__ G3, const float* __restrict__ G4) {
  int e = blockIdx.x * 256 + threadIdx.x;
  int col = e & 255, row = e >> 8;
  int s = row & 3, cd = row >> 2;
  int c = cd >> 4, d = cd & 15, k = col >> 4, l = col & 15;
  float acc = 0.f;
#pragma unroll
  for (int tt = 0; tt < 4; ++tt)
    acc += G3[((c * 16 + k) * 4 + s) * 4 + tt] * G4[(d * 16 + l) * 4 + tt];
  g_H34[(row << 8) | (col & ~31) | perm32(col & 31)] = rna_tf32(acc);
}
__global__ void prep_h12(const float* __restrict__ G1, const float* __restrict__ G2) {
  int e = blockIdx.x * 256 + threadIdx.x;
  int ab = e >> 10, k = e & 1023;
  int s = k >> 8, ij = k & 255;
  int a = ab >> 4, b = ab & 15, i = ij >> 4, j = ij & 15;
  float acc = 0.f;
#pragma unroll
  for (int r = 0; r < 4; ++r)
    acc += G1[(a * 16 + i) * 4 + r] * G2[((b * 16 + j) * 4 + r) * 4 + s];
  g_H12[(ab << 10) | (k & ~31) | perm32(k & 31)] = rna_tf32(acc);
}
__global__ __launch_bounds__(256) void round_x(const float* __restrict__ x) {
  size_t idx = (size_t)blockIdx.x * 256 + threadIdx.x;
  float4 v = *(const float4*)(x + idx * 4);
  size_t e = idx * 4;
  // kl is the fastest dim; e%32 == kl%32. v spans k = v0..v0+3 (v0%4==0):
  // p(v0+j) = j*8 + (v0>>2)
  float* o = g_Xr + (e & ~(size_t)31) + (int)((e & 31) >> 2);
  o[0]  = rna_tf32(v.x);
  o[8]  = rna_tf32(v.y);
  o[16] = rna_tf32(v.z);
  o[24] = rna_tf32(v.w);
}

// ---------------- batched GEMM: C[n] = A . B[n]^T ----------------
// A [Mtotal x K] K-major(permuted); B[n] [256 x K] K-major(permuted);
// C[n] [Mtotal x 256]. CTA tile 256(m) x 128(n), 8 warps of 64x64.
#define PAD 36
#define A_F 9216   // 256*36 floats
#define B_F 4608   // 128*36
#define STG_F 13824

__global__ __launch_bounds__(256, 1) void tt_gemm(
    const float* __restrict__ A, const float* __restrict__ Bbase, long long bStride,
    float* __restrict__ Cbase, long long cStride, int K,
    const float* __restrict__ bias, int permOut) {
  extern __shared__ __align__(16) float sm[];
  const int t = threadIdx.x;
  const int lane = t & 31, wid = t >> 5;
  const int grp = lane >> 2, tg = lane & 3;
  const int nt = blockIdx.x & 1, mt = blockIdx.x >> 1;
  const int n = blockIdx.y;
  const int wm = (wid & 3) * 64, wn = (wid >> 2) * 64;

  const float* Am = A + (long long)mt * 256 * K;
  const float* Bn = Bbase + (long long)n * bStride + (long long)nt * 128 * K;

  const int srow = t >> 3, sq = t & 7;
  const uint32_t base = smem_u32(sm);
  const uint32_t stA = base + (uint32_t)(srow * PAD + sq * 4) * 4u;
  const uint32_t stB = stA + A_F * 4u;

  float acc[4][8][4];
#pragma unroll
  for (int mi = 0; mi < 4; ++mi)
#pragma unroll
    for (int ni = 0; ni < 8; ++ni)
#pragma unroll
      for (int q = 0; q < 4; ++q) acc[mi][ni][q] = 0.f;

  const int nch = K >> 5;

#pragma unroll
  for (int pch = 0; pch < 2; ++pch) {
    const float* ga = Am + pch * 32;
    const float* gb = Bn + pch * 32;
    const uint32_t so = (uint32_t)pch * STG_F * 4u;
#pragma unroll
    for (int rep = 0; rep < 8; ++rep)
      cp16(stA + so + rep * 32u * PAD * 4u, ga + (long long)(srow + rep * 32) * K + sq * 4);
#pragma unroll
    for (int rep = 0; rep < 4; ++rep)
      cp16(stB + so + rep * 32u * PAD * 4u, gb + (long long)(srow + rep * 32) * K + sq * 4);
    asm volatile("cp.async.commit_group;" ::: "memory");
  }

  for (int ch = 0; ch < nch; ++ch) {
    const int st = ch & 1;
    asm volatile("cp.async.wait_group 1;" ::: "memory");
    __syncthreads();

    const float* sA = sm + st * STG_F;
    const float* sB = sA + A_F;
#pragma unroll
    for (int sel = 0; sel < 2; ++sel) {
      float4 alo[4], ahi[4], bb[8];
#pragma unroll
      for (int mi = 0; mi < 4; ++mi) {
        const float* pa = sA + (wm + mi * 16 + grp) * PAD + tg * 8 + sel * 4;
        alo[mi] = *(const float4*)pa;
        ahi[mi] = *(const float4*)(pa + 8 * PAD);
      }
#pragma unroll
      for (int ni = 0; ni < 8; ++ni)
        bb[ni] = *(const float4*)(sB + (wn + ni * 8 + grp) * PAD + tg * 8 + sel * 4);
      // kkA = 2*sel : A frag = (lo.x, hi.x, lo.y, hi.y), B = (b.x, b.y)
#pragma unroll
      for (int mi = 0; mi < 4; ++mi) {
        uint32_t a[4] = { __float_as_uint(alo[mi].x), __float_as_uint(ahi[mi].x),
                          __float_as_uint(alo[mi].y), __float_as_uint(ahi[mi].y) };
#pragma unroll
        for (int ni = 0; ni < 8; ++ni) {
          uint32_t b[2] = { __float_as_uint(bb[ni].x), __float_as_uint(bb[ni].y) };
          mma_tf32(acc[mi][ni], a, b);
        }
      }
      // kkB = 2*sel+1 : (.z, .w)
#pragma unroll
      for (int mi = 0; mi < 4; ++mi) {
        uint32_t a[4] = { __float_as_uint(alo[mi].z), __float_as_uint(ahi[mi].z),
                          __float_as_uint(alo[mi].w), __float_as_uint(ahi[mi].w) };
#pragma unroll
        for (int ni = 0; ni < 8; ++ni) {
          uint32_t b[2] = { __float_as_uint(bb[ni].z), __float_as_uint(bb[ni].w) };
          mma_tf32(acc[mi][ni], a, b);
        }
      }
    }
    __syncthreads();
    if (ch + 2 < nch) {
      const float* ga = Am + (ch + 2) * 32;
      const float* gb = Bn + (ch + 2) * 32;
      const uint32_t so = (uint32_t)st * STG_F * 4u;
#pragma unroll
      for (int rep = 0; rep < 8; ++rep)
        cp16(stA + so + rep * 32u * PAD * 4u, ga + (long long)(srow + rep * 32) * K + sq * 4);
#pragma unroll
      for (int rep = 0; rep < 4; ++rep)
        cp16(stB + so + rep * 32u * PAD * 4u, gb + (long long)(srow + rep * 32) * K + sq * 4);
    }
    asm volatile("cp.async.commit_group;" ::: "memory");
  }

  float* Cn = Cbase + (long long)n * cStride;
#pragma unroll
  for (int mi = 0; mi < 4; ++mi) {
    int r0 = mt * 256 + wm + mi * 16 + grp;
#pragma unroll
    for (int ni = 0; ni < 8; ++ni) {
      int col = nt * 128 + wn + ni * 8 + 2 * tg;
      float v0 = acc[mi][ni][0], v1 = acc[mi][ni][1];
      float v2 = acc[mi][ni][2], v3 = acc[mi][ni][3];
      if (bias) {
        v0 = fmaxf(v0 + bias[r0 * 256 + col], 0.f);
        v1 = fmaxf(v1 + bias[r0 * 256 + col + 1], 0.f);
        v2 = fmaxf(v2 + bias[(r0 + 8) * 256 + col], 0.f);
        v3 = fmaxf(v3 + bias[(r0 + 8) * 256 + col + 1], 0.f);
        *(float2*)(Cn + (long long)r0 * 256 + col) = make_float2(v0, v1);
        *(float2*)(Cn + (long long)(r0 + 8) * 256 + col) = make_float2(v2, v3);
      } else if (permOut) {
        // K-permute the output column (col even -> p(col+1) = p(col)+8)
        int p0 = (col & ~31) | perm32(col & 31);
        float* c0 = Cn + (long long)r0 * 256;
        float* c1 = Cn + (long long)(r0 + 8) * 256;
        c0[p0]     = rna_tf32(v0);
        c0[p0 + 8] = rna_tf32(v1);
        c1[p0]     = rna_tf32(v2);
        c1[p0 + 8] = rna_tf32(v3);
      }
    }
  }
}

// ---------------- launch ----------------
extern "C" void kernel_launch(void* const* d_in, const int* in_sizes, int n_in,
                              void* d_out, int out_size) {
  const float* x    = (const float*)d_in[0];
  const float* G1   = (const float*)d_in[1];
  const float* G2   = (const float*)d_in[2];
  const float* G3   = (const float*)d_in[3];
  const float* G4   = (const float*)d_in[4];
  const float* bias = (const float*)d_in[5];
  float* out = (float*)d_out;
  const int nb = in_sizes[0] / 65536;

  float *pH34, *pH12, *pM1, *pXr;
  cudaGetSymbolAddress((void**)&pH34, g_H34);
  cudaGetSymbolAddress((void**)&pH12, g_H12);
  cudaGetSymbolAddress((void**)&pM1, g_M1);
  cudaGetSymbolAddress((void**)&pXr, g_Xr);

  const int smem = 2 * STG_F * 4;  // 110592 B
  cudaFuncSetAttribute(tt_gemm, cudaFuncAttributeMaxDynamicSharedMemorySize, smem);

  prep_h34<<<1024, 256>>>(G3, G4);
  prep_h12<<<1024, 256>>>(G1, G2);
  round_x<<<in_sizes[0] / 1024, 256>>>(x);

  // GEMM1: M1[n] = H34 (1024xK256) . Xr[n]^T : 4 mtiles x 2 ntiles
  tt_gemm<<<dim3(8, nb), 256, smem>>>(pH34, pXr, 65536LL, pM1, 262144LL, 256,
                                      nullptr, 1);
  // GEMM2: out[n] = H12 (256xK1024) . M1[n]^T : 1 mtile x 2 ntiles
  tt_gemm<<<dim3(2, nb), 256, smem>>>(pH12, pM1, 262144LL, out, 65536LL, 1024,
                                      bias, 0);
}